// round 15
// baseline (speedup 1.0000x reference)
#include <cuda_runtime.h>
#include <cuda_fp16.h>
#include <cstdint>

#define BB 8
#define NN 2048
#define HID 768
#define NH 4
#define VOC 15
#define ROWS (BB*NN)
#define K2DIM (NH*HID)

typedef unsigned long long u64;
typedef unsigned int u32;

__device__ __half  g_x  [(size_t)ROWS*K2DIM];  // layer-1 out fp16 [m][k]
__device__ __half  g_Bh [(size_t)HID*K2DIM];   // Wout^T fp16 [n][k]
__device__ __half  g_Wh [(size_t)ROWS*HID];    // Wh fp16 [k][n]
__device__ __half  g_aw [(size_t)ROWS*NN];     // max-shifted attn weights fp16
__device__ float   g_den[ROWS];
__device__ float   g_w1[K2DIM], g_w2[K2DIM];
__device__ unsigned g_adjbits[ROWS*64];
__device__ int     g_C[ROWS*16];
__device__ int     g_H[BB*16];
__device__ float   g_T[NH*VOC*HID];
__device__ float   g_E[NH*VOC*16];
__device__ float   g_s1[ROWS];
__device__ float   g_s2[ROWS];

__device__ __forceinline__ float leakyf(float x){ return x > 0.f ? x : 0.2f*x; }

// Fast exp on the FMA pipe (no MUFU): magic-round exp2 split + deg-5 Taylor.
// Valid for x <= ~80; we clamp below at -100 (result ~0). Rel err ~3e-6.
__device__ __forceinline__ float fexp(float x){
    float t = fmaxf(x * 1.4426950408889634f, -100.f);
    float r = t + 12582912.f;                 // round-to-nearest-int magic
    int   n = __float_as_int(r) - 0x4B400000;
    float f = t - (r - 12582912.f);           // f in [-0.5, 0.5]
    float u = f * 0.6931471805599453f;
    float p = 1.f + u*(1.f + u*(0.5f + u*(0.16666667f + u*(0.041666667f + u*0.008333334f))));
    return p * __int_as_float((n + 127) << 23);
}
__device__ __forceinline__ float eluf(float x){ return x > 0.f ? x : (fexp(x)-1.f); }

__device__ __forceinline__ u32 smem_u32(const void* p){
    u32 a; asm("{ .reg .u64 t; cvta.to.shared.u64 t, %1; cvt.u32.u64 %0, t; }" : "=r"(a) : "l"(p));
    return a;
}

#define LDSM4(r, ad) \
    asm volatile("ldmatrix.sync.aligned.m8n8.x4.shared.b16 {%0,%1,%2,%3}, [%4];" \
        : "=r"((r)[0]),"=r"((r)[1]),"=r"((r)[2]),"=r"((r)[3]) : "r"(ad))
#define LDSM4T(r, ad) \
    asm volatile("ldmatrix.sync.aligned.m8n8.x4.trans.shared.b16 {%0,%1,%2,%3}, [%4];" \
        : "=r"((r)[0]),"=r"((r)[1]),"=r"((r)[2]),"=r"((r)[3]) : "r"(ad))
#define MMAF16(c, a, b0_, b1_) \
    asm volatile("mma.sync.aligned.m16n8k16.row.col.f32.f16.f16.f32 " \
        "{%0,%1,%2,%3}, {%4,%5,%6,%7}, {%8,%9}, {%0,%1,%2,%3};" \
        : "+f"((c)[0]),"+f"((c)[1]),"+f"((c)[2]),"+f"((c)[3]) \
        : "r"((a)[0]),"r"((a)[1]),"r"((a)[2]),"r"((a)[3]), "r"(b0_),"r"(b1_))

// -------- K0: zero out + s1/s2 ----------------------------------------------
__global__ void k_zero(float* __restrict__ out){
    int t = blockIdx.x*256 + threadIdx.x;
    if (t < ROWS){ g_s1[t] = 0.f; g_s2[t] = 0.f; }
    if (t < BB*HID) out[t] = 0.f;
}

// -------- K1: T_h = embed @ W_h ---------------------------------------------
__global__ void k_T(const float* __restrict__ embed, const float* __restrict__ Wheads){
    __shared__ float emb[VOC*HID];
    int h = blockIdx.y;
    int c = blockIdx.x*128 + threadIdx.x;
    for (int i = threadIdx.x; i < VOC*HID; i += 128) emb[i] = embed[i];
    __syncthreads();
    float acc[VOC];
    #pragma unroll
    for (int v = 0; v < VOC; v++) acc[v] = 0.f;
    const float* Wp = Wheads + (size_t)h*HID*HID + c;
    for (int k = 0; k < HID; k++){
        float w = Wp[(size_t)k*HID];
        #pragma unroll
        for (int v = 0; v < VOC; v++) acc[v] += emb[v*HID + k] * w;
    }
    #pragma unroll
    for (int v = 0; v < VOC; v++) g_T[(h*VOC + v)*HID + c] = acc[v];
}

// -------- K2: t1/t2 and E table (exact fp32 path — keep libm expf) ----------
__global__ void k_pre2(const float* __restrict__ aheads){
    __shared__ float t1s[NH*VOC], t2s[NH*VOC];
    int t = threadIdx.x;
    if (t < NH*VOC){
        int h = t / VOC, v = t % VOC;
        const float* Tp = g_T + (h*VOC + v)*HID;
        const float* a  = aheads + h*2*HID;
        float s1 = 0.f, s2 = 0.f;
        for (int c = 0; c < HID; c++){ s1 += Tp[c]*a[c]; s2 += Tp[c]*a[HID + c]; }
        t1s[t] = s1; t2s[t] = s2;
    }
    __syncthreads();
    for (int i = t; i < NH*VOC*VOC; i += blockDim.x){
        int h = i/(VOC*VOC); int u = (i/VOC)%VOC; int v = i%VOC;
        g_E[(h*VOC + u)*16 + v] = expf(leakyf(t1s[h*VOC + u] + t2s[h*VOC + v]));
    }
}

// -------- K3: adjacency bitmask + neighbor vocab counts ---------------------
__global__ void k_adj(const int* __restrict__ nf, const int* __restrict__ adj){
    __shared__ int fs[NN];
    __shared__ unsigned vmask[VOC][64];
    int b  = blockIdx.x >> 8;
    int r0 = (blockIdx.x & 255) * 8;
    int tid = threadIdx.x, lane = tid & 31, wi = tid >> 5;
    for (int i = tid; i < NN; i += 256) fs[i] = nf[b*NN + i];
    __syncthreads();
    for (int w = wi*8; w < wi*8 + 8; w++){
        int fj = fs[w*32 + lane];
        #pragma unroll
        for (int v = 0; v < VOC; v++){
            unsigned m = __ballot_sync(0xffffffffu, fj == v);
            if (lane == 0) vmask[v][w] = m;
        }
    }
    __syncthreads();
    if ((blockIdx.x & 255) == 0 && wi == 0){
        #pragma unroll
        for (int v = 0; v < VOC; v++){
            unsigned hv = __popc(vmask[v][lane]) + __popc(vmask[v][lane + 32]);
            hv = __reduce_add_sync(0xffffffffu, hv);
            if (lane == 0) g_H[b*16 + v] = (int)hv;
        }
    }
    int r = r0 + wi;
    const int* arow = adj + (size_t)(b*NN + r) * NN;
    unsigned am0 = 0, am1 = 0;
    for (int ch = 0; ch < 64; ch++){
        int a = arow[ch*32 + lane];
        unsigned m = __ballot_sync(0xffffffffu, a > 0);
        if (ch == lane)      am0 = m;
        if (ch == lane + 32) am1 = m;
    }
    unsigned* abp = g_adjbits + (size_t)(b*NN + r)*64;
    abp[lane] = am0; abp[32 + lane] = am1;
    #pragma unroll
    for (int v = 0; v < VOC; v++){
        unsigned c = __popc(am0 & vmask[v][lane]) + __popc(am1 & vmask[v][lane + 32]);
        c = __reduce_add_sync(0xffffffffu, c);
        if (lane == 0) g_C[(b*NN + r)*16 + v] = (int)c;
    }
}

// -------- K_prepB: Wout^T fp16 + w1/w2 = Wout @ a_out halves ----------------
__global__ void k_prepB(const float* __restrict__ Wout, const float* __restrict__ aout){
    int wi = threadIdx.x>>5, lane = threadIdx.x&31;
    int k = blockIdx.x*8 + wi;
    float a1s = 0.f, a2s = 0.f;
    const float* Wr = Wout + (size_t)k*HID;
    for (int n = lane; n < HID; n += 32){
        float v = Wr[n];
        a1s += v*aout[n]; a2s += v*aout[HID+n];
        g_Bh[(size_t)n*K2DIM + k] = __float2half(v);
    }
    #pragma unroll
    for (int o = 16; o; o >>= 1){
        a1s += __shfl_xor_sync(0xffffffffu, a1s, o);
        a2s += __shfl_xor_sync(0xffffffffu, a2s, o);
    }
    if (lane == 0){ g_w1[k] = a1s; g_w2[k] = a2s; }
}

// -------- K4: layer-1 -> fp16 + exact fp32 s1/s2 partials -------------------
__global__ void __launch_bounds__(256) k_l1(const int* __restrict__ nf){
    __shared__ float ws[128][16];
    __shared__ float Tt[VOC][128];
    __shared__ float w1s[128], w2s[128];
    int h = blockIdx.y / 6, ct = blockIdx.y % 6;
    int grow0 = blockIdx.x * 128;
    int b = grow0 / NN;
    int tid = threadIdx.x;
    int colbase = h*HID + ct*128;
    if (tid < 128){
        int grow = grow0 + tid;
        int fi = nf[grow];
        const float* Ep = g_E + (h*VOC + fi)*16;
        const int*   Cp = g_C + (size_t)grow*16;
        float cv[VOC]; float den = 0.f;
        #pragma unroll
        for (int v = 0; v < VOC; v++){ cv[v] = (float)Cp[v]; den += cv[v]*Ep[v]; }
        if (den > 0.f){
            float inv = 1.f/den;
            #pragma unroll
            for (int v = 0; v < VOC; v++) ws[tid][v] = cv[v]*Ep[v]*inv;
        } else {
            const int* Hp = g_H + b*16;
            #pragma unroll
            for (int v = 0; v < VOC; v++) ws[tid][v] = (float)Hp[v] * (1.f/(float)NN);
        }
        w1s[tid] = g_w1[colbase + tid];
        w2s[tid] = g_w2[colbase + tid];
    }
    for (int i = tid; i < VOC*128; i += 256){
        int v = i >> 7, c = i & 127;
        Tt[v][c] = g_T[(h*VOC + v)*HID + ct*128 + c];
    }
    __syncthreads();
    int tr = tid >> 4, tc = tid & 15;
    float acc[8][8];
    #pragma unroll
    for (int i = 0; i < 8; i++)
        #pragma unroll
        for (int j = 0; j < 8; j++) acc[i][j] = 0.f;
    #pragma unroll
    for (int v = 0; v < VOC; v++){
        float bb[8];
        #pragma unroll
        for (int j = 0; j < 8; j++) bb[j] = Tt[v][tc*8 + j];
        #pragma unroll
        for (int i = 0; i < 8; i++){
            float a = ws[tr*8 + i][v];
            #pragma unroll
            for (int j = 0; j < 8; j++) acc[i][j] += a*bb[j];
        }
    }
    #pragma unroll
    for (int i = 0; i < 8; i++){
        int row = grow0 + tr*8 + i;
        size_t base = (size_t)row*K2DIM + colbase + tc*8;
        float v[8];
        #pragma unroll
        for (int j = 0; j < 8; j++) v[j] = eluf(acc[i][j]);
        float p1 = 0.f, p2 = 0.f;
        #pragma unroll
        for (int j = 0; j < 8; j++){ p1 += v[j]*w1s[tc*8+j]; p2 += v[j]*w2s[tc*8+j]; }
        u32 hw[4];
        #pragma unroll
        for (int j2 = 0; j2 < 4; j2++){
            __half2 hp = __floats2half2_rn(v[2*j2], v[2*j2+1]);
            hw[j2] = *reinterpret_cast<u32*>(&hp);
        }
        *reinterpret_cast<uint4*>(g_x + base) = make_uint4(hw[0],hw[1],hw[2],hw[3]);
        #pragma unroll
        for (int o = 8; o; o >>= 1){
            p1 += __shfl_xor_sync(0xffffffffu, p1, o);
            p2 += __shfl_xor_sync(0xffffffffu, p2, o);
        }
        if (tc == 0){ atomicAdd(&g_s1[row], p1); atomicAdd(&g_s2[row], p2); }
    }
}

// -------- K5: fp16 HMMA GEMM -> Wh fp16 (1 MMA/tile) ------------------------
#define LDS2 40
#define ASZ (128*LDS2*2)          // 10240
#define STG (2*ASZ)               // 20480
#define GMM_SMEM (2*STG)          // 40960

__global__ void __launch_bounds__(256,2) k_gemm_mma(){
    extern __shared__ char sm[];
    u32 smb = smem_u32(sm);
    int tid = threadIdx.x, lane = tid&31, wid = tid>>5;
    int n0 = blockIdx.x*128, m0 = blockIdx.y*128;
    int wm = (wid>>2)*64, wn = (wid&3)*32;
    float acc[4][4][4];
    #pragma unroll
    for (int a = 0; a < 4; a++)
        #pragma unroll
        for (int b = 0; b < 4; b++)
            #pragma unroll
            for (int c = 0; c < 4; c++) acc[a][b][c] = 0.f;
    int arow = lane & 15,                  akh = (lane>>4)*8;
    int brow = ((lane>>4)<<3)+(lane&7),    bkh = ((lane>>3)&1)*8;
    #pragma unroll
    for (int it = 0; it < 2; it++){
        int ch = tid + it*256;
        int row = ch>>2, kc = (ch&3)*8;
        u32 so = (u32)(row*LDS2 + kc)*2;
        *(uint4*)(sm+so)     = *(const uint4*)(g_x  + (size_t)(m0+row)*K2DIM + kc);
        *(uint4*)(sm+so+ASZ) = *(const uint4*)(g_Bh + (size_t)(n0+row)*K2DIM + kc);
    }
    __syncthreads();
    const int NSt = K2DIM/32;   // 96
    uint4 rg[4];
    for (int s = 0; s < NSt; s++){
        int cur = s & 1;
        if (s + 1 < NSt){
            int k0 = (s+1)*32;
            #pragma unroll
            for (int it = 0; it < 2; it++){
                int ch = tid + it*256;
                int row = ch>>2, kc = (ch&3)*8;
                rg[it*2+0] = *(const uint4*)(g_x  + (size_t)(m0+row)*K2DIM + k0 + kc);
                rg[it*2+1] = *(const uint4*)(g_Bh + (size_t)(n0+row)*K2DIM + k0 + kc);
            }
        }
        u32 sb = smb + (u32)cur*STG;
        #pragma unroll
        for (int kh = 0; kh < 2; kh++){
            u32 ah[4][4];
            #pragma unroll
            for (int mt = 0; mt < 4; mt++){
                u32 ad = sb + (u32)(((wm + mt*16 + arow)*LDS2) + kh*16 + akh)*2;
                LDSM4(ah[mt], ad);
            }
            u32 bh[4][2];
            #pragma unroll
            for (int g = 0; g < 2; g++){
                u32 ad = sb + ASZ + (u32)(((wn + g*16 + brow)*LDS2) + kh*16 + bkh)*2;
                u32 t[4]; LDSM4(t, ad);
                bh[2*g][0]=t[0]; bh[2*g][1]=t[1]; bh[2*g+1][0]=t[2]; bh[2*g+1][1]=t[3];
            }
            #pragma unroll
            for (int mt = 0; mt < 4; mt++)
                #pragma unroll
                for (int nt = 0; nt < 4; nt++)
                    MMAF16(acc[mt][nt], ah[mt], bh[nt][0], bh[nt][1]);
        }
        if (s + 1 < NSt){
            u32 nb = (u32)(cur^1)*STG;
            #pragma unroll
            for (int it = 0; it < 2; it++){
                int ch = tid + it*256;
                int row = ch>>2, kc = (ch&3)*8;
                u32 so = nb + (u32)(row*LDS2 + kc)*2;
                *(uint4*)(sm+so)     = rg[it*2+0];
                *(uint4*)(sm+so+ASZ) = rg[it*2+1];
            }
        }
        __syncthreads();
    }
    int rbase = m0 + wm + (lane>>2);
    int cbase = n0 + wn + (lane&3)*2;
    #pragma unroll
    for (int mt = 0; mt < 4; mt++)
        #pragma unroll
        for (int nt = 0; nt < 4; nt++){
            int c = cbase + nt*8;
            #pragma unroll
            for (int half = 0; half < 2; half++){
                int r = rbase + mt*16 + half*8;
                __half2 hp = __floats2half2_rn(acc[mt][nt][half*2], acc[mt][nt][half*2+1]);
                *reinterpret_cast<u32*>(g_Wh + (size_t)r*HID + c) = *reinterpret_cast<u32*>(&hp);
            }
        }
}

// -------- K6: max-shifted attention weights (fp16) + denominators -----------
__global__ void k_aw(){
    __shared__ float s2s[NN];
    __shared__ unsigned aws[8][64];
    int tid = threadIdx.x, wid = tid>>5, lane = tid&31;
    int row0 = blockIdx.x*8;
    int b = row0 >> 11;
    for (int i = tid; i < NN; i += 256) s2s[i] = g_s2[b*NN + i];
    for (int i = tid; i < 512; i += 256) aws[i>>6][i&63] = g_adjbits[(size_t)row0*64 + i];
    __syncthreads();
    int row = row0 + wid;
    float s1r = g_s1[row];
    __half* awp = g_aw + (size_t)row*NN;
    // pass 1: row max of leaky(s1+s2) over neighbors
    float m = -1e30f;
    for (int w = 0; w < 64; w++){
        unsigned word = aws[wid][w];
        if ((word >> lane) & 1u)
            m = fmaxf(m, leakyf(s1r + s2s[w*32 + lane]));
    }
    #pragma unroll
    for (int o = 16; o; o >>= 1) m = fmaxf(m, __shfl_xor_sync(0xffffffffu, m, o));
    // pass 2: exp(x - m) via FMA-pipe fexp, den, fp16 store
    float den = 0.f;
    for (int w = 0; w < 64; w++){
        unsigned word = aws[wid][w];
        int col = w*32 + lane;
        float wv = 0.f;
        if ((word >> lane) & 1u){
            wv = fexp(leakyf(s1r + s2s[col]) - m);
            den += wv;
        }
        awp[col] = __float2half(wv);
    }
    #pragma unroll
    for (int o = 16; o; o >>= 1) den += __shfl_xor_sync(0xffffffffu, den, o);
    if (lane == 0) g_den[row] = den;
}

// -------- K7: fp16 HMMA attention GEMM + elu + mean pool --------------------
#define ALDA 40
#define BLDB 136
#define AT_A (128*ALDA*2)
#define AT_B (32*BLDB*2)
#define AT_ST (AT_A + AT_B)
#define ATT_SMEM (2*AT_ST)

__global__ void __launch_bounds__(256,2) k_attn_mma(float* __restrict__ out){
    extern __shared__ char sm[];
    __shared__ float colsum[128];
    u32 smb = smem_u32(sm);
    int tid = threadIdx.x, lane = tid&31, wid = tid>>5;
    int it = blockIdx.x, ct = blockIdx.y, b = blockIdx.z;
    int grow0 = b*NN + it*128;
    int wm = (wid>>2)*64, wn = (wid&3)*32;
    if (tid < 128) colsum[tid] = 0.f;
    float acc[4][4][4];
    #pragma unroll
    for (int a = 0; a < 4; a++)
        #pragma unroll
        for (int b2 = 0; b2 < 4; b2++)
            #pragma unroll
            for (int c = 0; c < 4; c++) acc[a][b2][c] = 0.f;
    const __half* Abase = g_aw + (size_t)grow0*NN;
    const __half* Bbase = g_Wh + (size_t)(b*NN)*HID + ct*128;
    int arow = lane&15, akh = (lane>>4)*8;
    int bkr = lane&15, bnh = (lane>>4)*8;
    #pragma unroll
    for (int it2 = 0; it2 < 2; it2++){
        int ch = tid + it2*256;
        int row = ch>>2, kc = (ch&3)*8;
        *(uint4*)(sm + (u32)(row*ALDA + kc)*2) = *(const uint4*)(Abase + (size_t)row*NN + kc);
        int kr = ch>>4, cc = (ch&15)*8;
        *(uint4*)(sm + AT_A + (u32)(kr*BLDB + cc)*2) = *(const uint4*)(Bbase + (size_t)kr*HID + cc);
    }
    __syncthreads();
    const int NSt = NN/32;  // 64
    uint4 rg[4];
    for (int s = 0; s < NSt; s++){
        int cur = s & 1;
        if (s + 1 < NSt){
            int k0 = (s+1)*32;
            #pragma unroll
            for (int it2 = 0; it2 < 2; it2++){
                int ch = tid + it2*256;
                int row = ch>>2, kc = (ch&3)*8;
                rg[it2*2+0] = *(const uint4*)(Abase + (size_t)row*NN + k0 + kc);
                int kr = ch>>4, cc = (ch&15)*8;
                rg[it2*2+1] = *(const uint4*)(Bbase + (size_t)(k0+kr)*HID + cc);
            }
        }
        u32 sb = smb + (u32)cur*AT_ST;
        #pragma unroll
        for (int kh = 0; kh < 2; kh++){
            u32 ah[4][4];
            #pragma unroll
            for (int mt = 0; mt < 4; mt++){
                u32 ad = sb + (u32)(((wm + mt*16 + arow)*ALDA) + kh*16 + akh)*2;
                LDSM4(ah[mt], ad);
            }
            u32 bh[4][2];
            #pragma unroll
            for (int g = 0; g < 2; g++){
                u32 ad = sb + AT_A + (u32)(((kh*16 + bkr)*BLDB) + wn + g*16 + bnh)*2;
                u32 t[4];  LDSM4T(t, ad);
                bh[2*g][0]=t[0]; bh[2*g][1]=t[1]; bh[2*g+1][0]=t[2]; bh[2*g+1][1]=t[3];
            }
            #pragma unroll
            for (int mt = 0; mt < 4; mt++)
                #pragma unroll
                for (int nt = 0; nt < 4; nt++)
                    MMAF16(acc[mt][nt], ah[mt], bh[nt][0], bh[nt][1]);
        }
        if (s + 1 < NSt){
            u32 nb = (u32)(cur^1)*AT_ST;
            #pragma unroll
            for (int it2 = 0; it2 < 2; it2++){
                int ch = tid + it2*256;
                int row = ch>>2, kc = (ch&3)*8;
                *(uint4*)(sm + nb + (u32)(row*ALDA + kc)*2) = rg[it2*2+0];
                int kr = ch>>4, cc = (ch&15)*8;
                *(uint4*)(sm + nb + AT_A + (u32)(kr*BLDB + cc)*2) = rg[it2*2+1];
            }
        }
        __syncthreads();
    }
    float invd[4][2];
    #pragma unroll
    for (int mt = 0; mt < 4; mt++){
        int r = grow0 + wm + mt*16 + (lane>>2);
        float d0 = g_den[r], d1 = g_den[r+8];
        invd[mt][0] = d0 > 0.f ? 1.f/d0 : 0.f;
        invd[mt][1] = d1 > 0.f ? 1.f/d1 : 0.f;
    }
    #pragma unroll
    for (int nt = 0; nt < 4; nt++){
        float cs0 = 0.f, cs1 = 0.f;
        #pragma unroll
        for (int mt = 0; mt < 4; mt++){
            cs0 += eluf(acc[mt][nt][0]*invd[mt][0]) + eluf(acc[mt][nt][2]*invd[mt][1]);
            cs1 += eluf(acc[mt][nt][1]*invd[mt][0]) + eluf(acc[mt][nt][3]*invd[mt][1]);
        }
        int c = wn + nt*8 + (lane&3)*2;
        atomicAdd(&colsum[c], cs0);
        atomicAdd(&colsum[c+1], cs1);
    }
    __syncthreads();
    if (tid < 128)
        atomicAdd(&out[b*HID + ct*128 + tid], colsum[tid] * (1.f/(float)NN));
}

// -------- launch -------------------------------------------------------------
extern "C" void kernel_launch(void* const* d_in, const int* in_sizes, int n_in,
                              void* d_out, int out_size){
    const int*   nf     = (const int*)d_in[0];
    const int*   adj    = (const int*)d_in[1];
    const float* embed  = (const float*)d_in[2];
    const float* Wheads = (const float*)d_in[3];
    const float* aheads = (const float*)d_in[4];
    const float* Wout   = (const float*)d_in[5];
    const float* aout   = (const float*)d_in[6];
    float* out = (float*)d_out;

    cudaFuncSetAttribute(k_gemm_mma, cudaFuncAttributeMaxDynamicSharedMemorySize, GMM_SMEM);
    cudaFuncSetAttribute(k_attn_mma, cudaFuncAttributeMaxDynamicSharedMemorySize, ATT_SMEM);

    k_zero<<<64, 256>>>(out);
    k_T   <<<dim3(6, 4), 128>>>(embed, Wheads);
    k_pre2<<<1, 64>>>(aheads);
    k_adj <<<2048, 256>>>(nf, adj);
    k_prepB<<<384, 256>>>(Wout, aout);
    k_l1  <<<dim3(128, 24), 256>>>(nf);
    k_aw  <<<2048, 256>>>();
    k_gemm_mma<<<dim3(6, 128), 256, GMM_SMEM>>>();
    k_attn_mma<<<dim3(16, 6, 8), 256, ATT_SMEM>>>(out);
}

// round 17
// speedup vs baseline: 1.0282x; 1.0282x over previous
#include <cuda_runtime.h>
#include <cuda_fp16.h>
#include <cstdint>

#define BB 8
#define NN 2048
#define HID 768
#define NH 4
#define VOC 15
#define ROWS (BB*NN)
#define K2DIM (NH*HID)

typedef unsigned long long u64;
typedef unsigned int u32;

__device__ __half  g_x  [(size_t)ROWS*K2DIM];  // layer-1 out fp16 [m][k]
__device__ __half  g_Bh [(size_t)HID*K2DIM];   // Wout^T fp16 [n][k]
__device__ __half  g_Wh [(size_t)ROWS*HID];    // Wh fp16 [k][n]
__device__ __half  g_aw [(size_t)ROWS*NN];     // max-shifted attn weights fp16
__device__ float   g_den[ROWS];
__device__ float   g_w1[K2DIM], g_w2[K2DIM];
__device__ unsigned g_adjbits[ROWS*64];
__device__ int     g_C[ROWS*16];
__device__ int     g_H[BB*16];
__device__ float   g_T[NH*VOC*HID];
__device__ float   g_E[NH*VOC*16];
__device__ float   g_s1[ROWS];
__device__ float   g_s2[ROWS];

__device__ __forceinline__ float leakyf(float x){ return x > 0.f ? x : 0.2f*x; }

// Fast exp on the FMA pipe: magic-round exp2 split + deg-5 Taylor. Rel err ~3e-6.
__device__ __forceinline__ float fexp(float x){
    float t = fmaxf(x * 1.4426950408889634f, -100.f);
    float r = t + 12582912.f;
    int   n = __float_as_int(r) - 0x4B400000;
    float f = t - (r - 12582912.f);
    float u = f * 0.6931471805599453f;
    float p = 1.f + u*(1.f + u*(0.5f + u*(0.16666667f + u*(0.041666667f + u*0.008333334f))));
    return p * __int_as_float((n + 127) << 23);
}
__device__ __forceinline__ float eluf(float x){ return x > 0.f ? x : (fexp(x)-1.f); }

__device__ __forceinline__ u32 smem_u32(const void* p){
    u32 a; asm("{ .reg .u64 t; cvta.to.shared.u64 t, %1; cvt.u32.u64 %0, t; }" : "=r"(a) : "l"(p));
    return a;
}

#define LDSM4(r, ad) \
    asm volatile("ldmatrix.sync.aligned.m8n8.x4.shared.b16 {%0,%1,%2,%3}, [%4];" \
        : "=r"((r)[0]),"=r"((r)[1]),"=r"((r)[2]),"=r"((r)[3]) : "r"(ad))
#define LDSM4T(r, ad) \
    asm volatile("ldmatrix.sync.aligned.m8n8.x4.trans.shared.b16 {%0,%1,%2,%3}, [%4];" \
        : "=r"((r)[0]),"=r"((r)[1]),"=r"((r)[2]),"=r"((r)[3]) : "r"(ad))
#define MMAF16(c, a, b0_, b1_) \
    asm volatile("mma.sync.aligned.m16n8k16.row.col.f32.f16.f16.f32 " \
        "{%0,%1,%2,%3}, {%4,%5,%6,%7}, {%8,%9}, {%0,%1,%2,%3};" \
        : "+f"((c)[0]),"+f"((c)[1]),"+f"((c)[2]),"+f"((c)[3]) \
        : "r"((a)[0]),"r"((a)[1]),"r"((a)[2]),"r"((a)[3]), "r"(b0_),"r"(b1_))

// =============== U_FRONT: fused k_adj + k_prepB + k_zero =====================
__device__ void adj_body(int bid, const int* __restrict__ nf, const int* __restrict__ adj,
                         int* fs, unsigned (*vmask)[64]){
    int b  = bid >> 8;
    int r0 = (bid & 255) * 8;
    int tid = threadIdx.x, lane = tid & 31, wi = tid >> 5;
    for (int i = tid; i < NN; i += 256) fs[i] = nf[b*NN + i];
    __syncthreads();
    for (int w = wi*8; w < wi*8 + 8; w++){
        int fj = fs[w*32 + lane];
        #pragma unroll
        for (int v = 0; v < VOC; v++){
            unsigned m = __ballot_sync(0xffffffffu, fj == v);
            if (lane == 0) vmask[v][w] = m;
        }
    }
    __syncthreads();
    if ((bid & 255) == 0 && wi == 0){
        #pragma unroll
        for (int v = 0; v < VOC; v++){
            unsigned hv = __popc(vmask[v][lane]) + __popc(vmask[v][lane + 32]);
            hv = __reduce_add_sync(0xffffffffu, hv);
            if (lane == 0) g_H[b*16 + v] = (int)hv;
        }
    }
    int r = r0 + wi;
    const int* arow = adj + (size_t)(b*NN + r) * NN;
    unsigned am0 = 0, am1 = 0;
    for (int ch = 0; ch < 64; ch++){
        int a = arow[ch*32 + lane];
        unsigned m = __ballot_sync(0xffffffffu, a > 0);
        if (ch == lane)      am0 = m;
        if (ch == lane + 32) am1 = m;
    }
    unsigned* abp = g_adjbits + (size_t)(b*NN + r)*64;
    abp[lane] = am0; abp[32 + lane] = am1;
    #pragma unroll
    for (int v = 0; v < VOC; v++){
        unsigned c = __popc(am0 & vmask[v][lane]) + __popc(am1 & vmask[v][lane + 32]);
        c = __reduce_add_sync(0xffffffffu, c);
        if (lane == 0) g_C[(b*NN + r)*16 + v] = (int)c;
    }
}

__device__ void prepB_body(int abid, const float* __restrict__ Wout, const float* __restrict__ aout){
    int wi = threadIdx.x>>5, lane = threadIdx.x&31;
    int k = abid*8 + wi;
    float a1s = 0.f, a2s = 0.f;
    const float* Wr = Wout + (size_t)k*HID;
    for (int n = lane; n < HID; n += 32){
        float v = Wr[n];
        a1s += v*aout[n]; a2s += v*aout[HID+n];
        g_Bh[(size_t)n*K2DIM + k] = __float2half(v);
    }
    #pragma unroll
    for (int o = 16; o; o >>= 1){
        a1s += __shfl_xor_sync(0xffffffffu, a1s, o);
        a2s += __shfl_xor_sync(0xffffffffu, a2s, o);
    }
    if (lane == 0){ g_w1[k] = a1s; g_w2[k] = a2s; }
}

__global__ void __launch_bounds__(256) u_front(const int* __restrict__ nf,
                                               const int* __restrict__ adj,
                                               const float* __restrict__ Wout,
                                               const float* __restrict__ aout,
                                               float* __restrict__ out){
    __shared__ int fs[NN];
    __shared__ unsigned vmask[VOC][64];
    int bid = blockIdx.x;
    if (bid < 2048){
        adj_body(bid, nf, adj, fs, vmask);
    } else if (bid < 2432){
        prepB_body(bid - 2048, Wout, aout);
    } else {
        int t = (bid - 2432)*256 + threadIdx.x;
        if (t < ROWS){ g_s1[t] = 0.f; g_s2[t] = 0.f; }
        if (t < BB*HID) out[t] = 0.f;
    }
}

// -------- K1: T_h = embed @ W_h ---------------------------------------------
__global__ void k_T(const float* __restrict__ embed, const float* __restrict__ Wheads){
    __shared__ float emb[VOC*HID];
    int h = blockIdx.y;
    int c = blockIdx.x*128 + threadIdx.x;
    for (int i = threadIdx.x; i < VOC*HID; i += 128) emb[i] = embed[i];
    __syncthreads();
    float acc[VOC];
    #pragma unroll
    for (int v = 0; v < VOC; v++) acc[v] = 0.f;
    const float* Wp = Wheads + (size_t)h*HID*HID + c;
    for (int k = 0; k < HID; k++){
        float w = Wp[(size_t)k*HID];
        #pragma unroll
        for (int v = 0; v < VOC; v++) acc[v] += emb[v*HID + k] * w;
    }
    #pragma unroll
    for (int v = 0; v < VOC; v++) g_T[(h*VOC + v)*HID + c] = acc[v];
}

// -------- K2: t1/t2 and E table (exact fp32 path) ---------------------------
__global__ void k_pre2(const float* __restrict__ aheads){
    __shared__ float t1s[NH*VOC], t2s[NH*VOC];
    int t = threadIdx.x;
    if (t < NH*VOC){
        int h = t / VOC, v = t % VOC;
        const float* Tp = g_T + (h*VOC + v)*HID;
        const float* a  = aheads + h*2*HID;
        float s1 = 0.f, s2 = 0.f;
        for (int c = 0; c < HID; c++){ s1 += Tp[c]*a[c]; s2 += Tp[c]*a[HID + c]; }
        t1s[t] = s1; t2s[t] = s2;
    }
    __syncthreads();
    for (int i = t; i < NH*VOC*VOC; i += blockDim.x){
        int h = i/(VOC*VOC); int u = (i/VOC)%VOC; int v = i%VOC;
        g_E[(h*VOC + u)*16 + v] = expf(leakyf(t1s[h*VOC + u] + t2s[h*VOC + v]));
    }
}

// -------- K4: layer-1 -> fp16 + exact fp32 s1/s2 partials -------------------
__global__ void __launch_bounds__(256) k_l1(const int* __restrict__ nf){
    __shared__ float ws[128][16];
    __shared__ float Tt[VOC][128];
    __shared__ float w1s[128], w2s[128];
    int h = blockIdx.y / 6, ct = blockIdx.y % 6;
    int grow0 = blockIdx.x * 128;
    int b = grow0 / NN;
    int tid = threadIdx.x;
    int colbase = h*HID + ct*128;
    if (tid < 128){
        int grow = grow0 + tid;
        int fi = nf[grow];
        const float* Ep = g_E + (h*VOC + fi)*16;
        const int*   Cp = g_C + (size_t)grow*16;
        float cv[VOC]; float den = 0.f;
        #pragma unroll
        for (int v = 0; v < VOC; v++){ cv[v] = (float)Cp[v]; den += cv[v]*Ep[v]; }
        if (den > 0.f){
            float inv = 1.f/den;
            #pragma unroll
            for (int v = 0; v < VOC; v++) ws[tid][v] = cv[v]*Ep[v]*inv;
        } else {
            const int* Hp = g_H + b*16;
            #pragma unroll
            for (int v = 0; v < VOC; v++) ws[tid][v] = (float)Hp[v] * (1.f/(float)NN);
        }
        w1s[tid] = g_w1[colbase + tid];
        w2s[tid] = g_w2[colbase + tid];
    }
    for (int i = tid; i < VOC*128; i += 256){
        int v = i >> 7, c = i & 127;
        Tt[v][c] = g_T[(h*VOC + v)*HID + ct*128 + c];
    }
    __syncthreads();
    int tr = tid >> 4, tc = tid & 15;
    float acc[8][8];
    #pragma unroll
    for (int i = 0; i < 8; i++)
        #pragma unroll
        for (int j = 0; j < 8; j++) acc[i][j] = 0.f;
    #pragma unroll
    for (int v = 0; v < VOC; v++){
        float bb[8];
        #pragma unroll
        for (int j = 0; j < 8; j++) bb[j] = Tt[v][tc*8 + j];
        #pragma unroll
        for (int i = 0; i < 8; i++){
            float a = ws[tr*8 + i][v];
            #pragma unroll
            for (int j = 0; j < 8; j++) acc[i][j] += a*bb[j];
        }
    }
    #pragma unroll
    for (int i = 0; i < 8; i++){
        int row = grow0 + tr*8 + i;
        size_t base = (size_t)row*K2DIM + colbase + tc*8;
        float v[8];
        #pragma unroll
        for (int j = 0; j < 8; j++) v[j] = eluf(acc[i][j]);
        float p1 = 0.f, p2 = 0.f;
        #pragma unroll
        for (int j = 0; j < 8; j++){ p1 += v[j]*w1s[tc*8+j]; p2 += v[j]*w2s[tc*8+j]; }
        u32 hw[4];
        #pragma unroll
        for (int j2 = 0; j2 < 4; j2++){
            __half2 hp = __floats2half2_rn(v[2*j2], v[2*j2+1]);
            hw[j2] = *reinterpret_cast<u32*>(&hp);
        }
        *reinterpret_cast<uint4*>(g_x + base) = make_uint4(hw[0],hw[1],hw[2],hw[3]);
        #pragma unroll
        for (int o = 8; o; o >>= 1){
            p1 += __shfl_xor_sync(0xffffffffu, p1, o);
            p2 += __shfl_xor_sync(0xffffffffu, p2, o);
        }
        if (tc == 0){ atomicAdd(&g_s1[row], p1); atomicAdd(&g_s2[row], p2); }
    }
}

// =============== U_BACK: fused fp16 GEMM (blocks 0-767) + k_aw (768-2815) ====
#define LDS2 40
#define ASZ (128*LDS2*2)          // 10240
#define STG (2*ASZ)               // 20480
#define GMM_SMEM (2*STG)          // 40960

__device__ void gemm_body(char* sm, int gbid){
    u32 smb = smem_u32(sm);
    int tid = threadIdx.x, lane = tid&31, wid = tid>>5;
    int n0 = (gbid % 6)*128, m0 = (gbid / 6)*128;
    int wm = (wid>>2)*64, wn = (wid&3)*32;
    float acc[4][4][4];
    #pragma unroll
    for (int a = 0; a < 4; a++)
        #pragma unroll
        for (int b = 0; b < 4; b++)
            #pragma unroll
            for (int c = 0; c < 4; c++) acc[a][b][c] = 0.f;
    int arow = lane & 15,                  akh = (lane>>4)*8;
    int brow = ((lane>>4)<<3)+(lane&7),    bkh = ((lane>>3)&1)*8;
    #pragma unroll
    for (int it = 0; it < 2; it++){
        int ch = tid + it*256;
        int row = ch>>2, kc = (ch&3)*8;
        u32 so = (u32)(row*LDS2 + kc)*2;
        *(uint4*)(sm+so)     = *(const uint4*)(g_x  + (size_t)(m0+row)*K2DIM + kc);
        *(uint4*)(sm+so+ASZ) = *(const uint4*)(g_Bh + (size_t)(n0+row)*K2DIM + kc);
    }
    __syncthreads();
    const int NSt = K2DIM/32;   // 96
    uint4 rg[4];
    for (int s = 0; s < NSt; s++){
        int cur = s & 1;
        if (s + 1 < NSt){
            int k0 = (s+1)*32;
            #pragma unroll
            for (int it = 0; it < 2; it++){
                int ch = tid + it*256;
                int row = ch>>2, kc = (ch&3)*8;
                rg[it*2+0] = *(const uint4*)(g_x  + (size_t)(m0+row)*K2DIM + k0 + kc);
                rg[it*2+1] = *(const uint4*)(g_Bh + (size_t)(n0+row)*K2DIM + k0 + kc);
            }
        }
        u32 sb = smb + (u32)cur*STG;
        #pragma unroll
        for (int kh = 0; kh < 2; kh++){
            u32 ah[4][4];
            #pragma unroll
            for (int mt = 0; mt < 4; mt++){
                u32 ad = sb + (u32)(((wm + mt*16 + arow)*LDS2) + kh*16 + akh)*2;
                LDSM4(ah[mt], ad);
            }
            u32 bh[4][2];
            #pragma unroll
            for (int g = 0; g < 2; g++){
                u32 ad = sb + ASZ + (u32)(((wn + g*16 + brow)*LDS2) + kh*16 + bkh)*2;
                u32 t[4]; LDSM4(t, ad);
                bh[2*g][0]=t[0]; bh[2*g][1]=t[1]; bh[2*g+1][0]=t[2]; bh[2*g+1][1]=t[3];
            }
            #pragma unroll
            for (int mt = 0; mt < 4; mt++)
                #pragma unroll
                for (int nt = 0; nt < 4; nt++)
                    MMAF16(acc[mt][nt], ah[mt], bh[nt][0], bh[nt][1]);
        }
        if (s + 1 < NSt){
            u32 nb = (u32)(cur^1)*STG;
            #pragma unroll
            for (int it = 0; it < 2; it++){
                int ch = tid + it*256;
                int row = ch>>2, kc = (ch&3)*8;
                u32 so = nb + (u32)(row*LDS2 + kc)*2;
                *(uint4*)(sm+so)     = rg[it*2+0];
                *(uint4*)(sm+so+ASZ) = rg[it*2+1];
            }
        }
        __syncthreads();
    }
    int rbase = m0 + wm + (lane>>2);
    int cbase = n0 + wn + (lane&3)*2;
    #pragma unroll
    for (int mt = 0; mt < 4; mt++)
        #pragma unroll
        for (int nt = 0; nt < 4; nt++){
            int c = cbase + nt*8;
            #pragma unroll
            for (int half = 0; half < 2; half++){
                int r = rbase + mt*16 + half*8;
                __half2 hp = __floats2half2_rn(acc[mt][nt][half*2], acc[mt][nt][half*2+1]);
                *reinterpret_cast<u32*>(g_Wh + (size_t)r*HID + c) = *reinterpret_cast<u32*>(&hp);
            }
        }
}

__device__ void aw_body(char* sm, int abid){
    float*    s2s = (float*)sm;              // 8192 B
    unsigned* aws = (unsigned*)(sm + 8192);  // 2048 B
    int tid = threadIdx.x, wid = tid>>5, lane = tid&31;
    int row0 = abid*8;
    int b = row0 >> 11;
    for (int i = tid; i < NN; i += 256) s2s[i] = g_s2[b*NN + i];
    for (int i = tid; i < 512; i += 256) aws[i] = g_adjbits[(size_t)row0*64 + i];
    __syncthreads();
    int row = row0 + wid;
    float s1r = g_s1[row];
    __half* awp = g_aw + (size_t)row*NN;
    float m = -1e30f;
    for (int w = 0; w < 64; w++){
        unsigned word = aws[wid*64 + w];
        if ((word >> lane) & 1u)
            m = fmaxf(m, leakyf(s1r + s2s[w*32 + lane]));
    }
    #pragma unroll
    for (int o = 16; o; o >>= 1) m = fmaxf(m, __shfl_xor_sync(0xffffffffu, m, o));
    float den = 0.f;
    for (int w = 0; w < 64; w++){
        unsigned word = aws[wid*64 + w];
        int col = w*32 + lane;
        float wv = 0.f;
        if ((word >> lane) & 1u){
            wv = fexp(leakyf(s1r + s2s[col]) - m);
            den += wv;
        }
        awp[col] = __float2half(wv);
    }
    #pragma unroll
    for (int o = 16; o; o >>= 1) den += __shfl_xor_sync(0xffffffffu, den, o);
    if (lane == 0) g_den[row] = den;
}

__global__ void __launch_bounds__(256,2) u_back(){
    extern __shared__ char sm[];
    int bid = blockIdx.x;
    if (bid < 768) gemm_body(sm, bid);
    else           aw_body(sm, bid - 768);
}

// -------- K7: fp16 HMMA attention GEMM + elu + mean pool --------------------
#define ALDA 40
#define BLDB 136
#define AT_A (128*ALDA*2)
#define AT_B (32*BLDB*2)
#define AT_ST (AT_A + AT_B)
#define ATT_SMEM (2*AT_ST)

__global__ void __launch_bounds__(256,2) k_attn_mma(float* __restrict__ out){
    extern __shared__ char sm[];
    __shared__ float colsum[128];
    u32 smb = smem_u32(sm);
    int tid = threadIdx.x, lane = tid&31, wid = tid>>5;
    int it = blockIdx.x, ct = blockIdx.y, b = blockIdx.z;
    int grow0 = b*NN + it*128;
    int wm = (wid>>2)*64, wn = (wid&3)*32;
    if (tid < 128) colsum[tid] = 0.f;
    float acc[4][4][4];
    #pragma unroll
    for (int a = 0; a < 4; a++)
        #pragma unroll
        for (int b2 = 0; b2 < 4; b2++)
            #pragma unroll
            for (int c = 0; c < 4; c++) acc[a][b2][c] = 0.f;
    const __half* Abase = g_aw + (size_t)grow0*NN;
    const __half* Bbase = g_Wh + (size_t)(b*NN)*HID + ct*128;
    int arow = lane&15, akh = (lane>>4)*8;
    int bkr = lane&15, bnh = (lane>>4)*8;
    #pragma unroll
    for (int it2 = 0; it2 < 2; it2++){
        int ch = tid + it2*256;
        int row = ch>>2, kc = (ch&3)*8;
        *(uint4*)(sm + (u32)(row*ALDA + kc)*2) = *(const uint4*)(Abase + (size_t)row*NN + kc);
        int kr = ch>>4, cc = (ch&15)*8;
        *(uint4*)(sm + AT_A + (u32)(kr*BLDB + cc)*2) = *(const uint4*)(Bbase + (size_t)kr*HID + cc);
    }
    __syncthreads();
    const int NSt = NN/32;  // 64
    uint4 rg[4];
    for (int s = 0; s < NSt; s++){
        int cur = s & 1;
        if (s + 1 < NSt){
            int k0 = (s+1)*32;
            #pragma unroll
            for (int it2 = 0; it2 < 2; it2++){
                int ch = tid + it2*256;
                int row = ch>>2, kc = (ch&3)*8;
                rg[it2*2+0] = *(const uint4*)(Abase + (size_t)row*NN + k0 + kc);
                int kr = ch>>4, cc = (ch&15)*8;
                rg[it2*2+1] = *(const uint4*)(Bbase + (size_t)(k0+kr)*HID + cc);
            }
        }
        u32 sb = smb + (u32)cur*AT_ST;
        #pragma unroll
        for (int kh = 0; kh < 2; kh++){
            u32 ah[4][4];
            #pragma unroll
            for (int mt = 0; mt < 4; mt++){
                u32 ad = sb + (u32)(((wm + mt*16 + arow)*ALDA) + kh*16 + akh)*2;
                LDSM4(ah[mt], ad);
            }
            u32 bh[4][2];
            #pragma unroll
            for (int g = 0; g < 2; g++){
                u32 ad = sb + AT_A + (u32)(((kh*16 + bkr)*BLDB) + wn + g*16 + bnh)*2;
                u32 t[4];  LDSM4T(t, ad);
                bh[2*g][0]=t[0]; bh[2*g][1]=t[1]; bh[2*g+1][0]=t[2]; bh[2*g+1][1]=t[3];
            }
            #pragma unroll
            for (int mt = 0; mt < 4; mt++)
                #pragma unroll
                for (int nt = 0; nt < 4; nt++)
                    MMAF16(acc[mt][nt], ah[mt], bh[nt][0], bh[nt][1]);
        }
        if (s + 1 < NSt){
            u32 nb = (u32)(cur^1)*AT_ST;
            #pragma unroll
            for (int it2 = 0; it2 < 2; it2++){
                int ch = tid + it2*256;
                int row = ch>>2, kc = (ch&3)*8;
                *(uint4*)(sm + nb + (u32)(row*ALDA + kc)*2) = rg[it2*2+0];
                int kr = ch>>4, cc = (ch&15)*8;
                *(uint4*)(sm + nb + AT_A + (u32)(kr*BLDB + cc)*2) = rg[it2*2+1];
            }
        }
        __syncthreads();
    }
    float invd[4][2];
    #pragma unroll
    for (int mt = 0; mt < 4; mt++){
        int r = grow0 + wm + mt*16 + (lane>>2);
        float d0 = g_den[r], d1 = g_den[r+8];
        invd[mt][0] = d0 > 0.f ? 1.f/d0 : 0.f;
        invd[mt][1] = d1 > 0.f ? 1.f/d1 : 0.f;
    }
    #pragma unroll
    for (int nt = 0; nt < 4; nt++){
        float cs0 = 0.f, cs1 = 0.f;
        #pragma unroll
        for (int mt = 0; mt < 4; mt++){
            cs0 += eluf(acc[mt][nt][0]*invd[mt][0]) + eluf(acc[mt][nt][2]*invd[mt][1]);
            cs1 += eluf(acc[mt][nt][1]*invd[mt][0]) + eluf(acc[mt][nt][3]*invd[mt][1]);
        }
        int c = wn + nt*8 + (lane&3)*2;
        atomicAdd(&colsum[c], cs0);
        atomicAdd(&colsum[c+1], cs1);
    }
    __syncthreads();
    if (tid < 128)
        atomicAdd(&out[b*HID + ct*128 + tid], colsum[tid] * (1.f/(float)NN));
}

// -------- launch -------------------------------------------------------------
extern "C" void kernel_launch(void* const* d_in, const int* in_sizes, int n_in,
                              void* d_out, int out_size){
    const int*   nf     = (const int*)d_in[0];
    const int*   adj    = (const int*)d_in[1];
    const float* embed  = (const float*)d_in[2];
    const float* Wheads = (const float*)d_in[3];
    const float* aheads = (const float*)d_in[4];
    const float* Wout   = (const float*)d_in[5];
    const float* aout   = (const float*)d_in[6];
    float* out = (float*)d_out;

    cudaFuncSetAttribute(u_back,     cudaFuncAttributeMaxDynamicSharedMemorySize, GMM_SMEM);
    cudaFuncSetAttribute(k_attn_mma, cudaFuncAttributeMaxDynamicSharedMemorySize, ATT_SMEM);

    u_front<<<2496, 256>>>(nf, adj, Wout, aout, out);
    k_T   <<<dim3(6, 4), 128>>>(embed, Wheads);
    k_pre2<<<1, 64>>>(aheads);
    k_l1  <<<dim3(128, 24), 256>>>(nf);
    u_back<<<2816, 256, GMM_SMEM>>>();
    k_attn_mma<<<dim3(16, 6, 8), 256, ATT_SMEM>>>(out);
}